// round 1
// baseline (speedup 1.0000x reference)
#include <cuda_runtime.h>

// Problem constants (fixed shapes from reference setup_inputs)
#define HDIM 2048
#define MTOT 16384          // B*S = 8*2048
#define COMBINED_ELEMS (MTOT * HDIM)   // 33554432
#define W_ELEMS (HDIM * HDIM)          // 4194304

// Scratch: W_sum = fixed_w + plastic_weights (16 MB), norm accumulator
__device__ float g_wsum[W_ELEMS];
__device__ float g_sumsq;

// ---------------------------------------------------------------------------
// Tiny kernels
// ---------------------------------------------------------------------------
__global__ void zero_acc_kernel() { g_sumsq = 0.0f; }

__global__ void wsum_kernel(const float* __restrict__ fw,
                            const float* __restrict__ pw) {
    int i = (blockIdx.x * blockDim.x + threadIdx.x) * 4;
    float4 a = *reinterpret_cast<const float4*>(&fw[i]);
    float4 b = *reinterpret_cast<const float4*>(&pw[i]);
    float4 o;
    o.x = a.x + b.x; o.y = a.y + b.y; o.z = a.z + b.z; o.w = a.w + b.w;
    *reinterpret_cast<float4*>(&g_wsum[i]) = o;
}

__global__ void scale_w_kernel(float* __restrict__ W) {
    float n = sqrtf(g_sumsq);
    float s = (n > 1.0f) ? (1.0f / n) : 1.0f;
    int i = (blockIdx.x * blockDim.x + threadIdx.x) * 4;
    float4 v = *reinterpret_cast<float4*>(&W[i]);
    v.x *= s; v.y *= s; v.z *= s; v.w *= s;
    *reinterpret_cast<float4*>(&W[i]) = v;
}

// ---------------------------------------------------------------------------
// GEMM1 (NT): C[m,n] = sum_k A[m,k] * Wsum[n,k] + bias[n]
// A = x [MTOT, HDIM], Wsum [HDIM, HDIM], C = combined [MTOT, HDIM]
// Tile 128x128x16, 256 threads, 8x8 microtile.
// ---------------------------------------------------------------------------
__global__ __launch_bounds__(256, 2)
void gemm1_nt(const float* __restrict__ A,
              const float* __restrict__ bias,
              float* __restrict__ C) {
    const int K = HDIM;
    __shared__ float As[16][132];   // [k][m] transposed, pad to break conflicts
    __shared__ float Bs[16][132];   // [k][n]

    const int tid = threadIdx.x;
    const int tx = tid & 15;        // n sub-tile
    const int ty = tid >> 4;        // m sub-tile
    const int m0 = blockIdx.y * 128;
    const int n0 = blockIdx.x * 128;

    float acc[8][8];
    #pragma unroll
    for (int i = 0; i < 8; i++)
        #pragma unroll
        for (int j = 0; j < 8; j++) acc[i][j] = 0.0f;

    for (int k0 = 0; k0 < K; k0 += 16) {
        #pragma unroll
        for (int s = 0; s < 2; s++) {
            int slot = tid + s * 256;     // 0..511
            int row = slot >> 2;          // 0..127
            int kq  = slot & 3;           // 0..3 (float4 within 16-wide k)
            float4 v = *reinterpret_cast<const float4*>(
                &A[(size_t)(m0 + row) * K + k0 + kq * 4]);
            As[kq * 4 + 0][row] = v.x;
            As[kq * 4 + 1][row] = v.y;
            As[kq * 4 + 2][row] = v.z;
            As[kq * 4 + 3][row] = v.w;
        }
        #pragma unroll
        for (int s = 0; s < 2; s++) {
            int slot = tid + s * 256;
            int row = slot >> 2;
            int kq  = slot & 3;
            float4 v = *reinterpret_cast<const float4*>(
                &g_wsum[(size_t)(n0 + row) * K + k0 + kq * 4]);
            Bs[kq * 4 + 0][row] = v.x;
            Bs[kq * 4 + 1][row] = v.y;
            Bs[kq * 4 + 2][row] = v.z;
            Bs[kq * 4 + 3][row] = v.w;
        }
        __syncthreads();

        #pragma unroll
        for (int kk = 0; kk < 16; kk++) {
            float a[8], b[8];
            *reinterpret_cast<float4*>(&a[0]) =
                *reinterpret_cast<const float4*>(&As[kk][ty * 8]);
            *reinterpret_cast<float4*>(&a[4]) =
                *reinterpret_cast<const float4*>(&As[kk][ty * 8 + 4]);
            *reinterpret_cast<float4*>(&b[0]) =
                *reinterpret_cast<const float4*>(&Bs[kk][tx * 8]);
            *reinterpret_cast<float4*>(&b[4]) =
                *reinterpret_cast<const float4*>(&Bs[kk][tx * 8 + 4]);
            #pragma unroll
            for (int i = 0; i < 8; i++)
                #pragma unroll
                for (int j = 0; j < 8; j++)
                    acc[i][j] += a[i] * b[j];
        }
        __syncthreads();
    }

    #pragma unroll
    for (int i = 0; i < 8; i++) {
        int m = m0 + ty * 8 + i;
        #pragma unroll
        for (int j = 0; j < 8; j += 4) {
            int n = n0 + tx * 8 + j;
            float4 o;
            o.x = acc[i][j + 0] + bias[n + 0];
            o.y = acc[i][j + 1] + bias[n + 1];
            o.z = acc[i][j + 2] + bias[n + 2];
            o.w = acc[i][j + 3] + bias[n + 3];
            *reinterpret_cast<float4*>(&C[(size_t)m * HDIM + n]) = o;
        }
    }
}

// ---------------------------------------------------------------------------
// GEMM2 (TN) + fused epilogue:
//   hebb[i,j] = (1/MTOT) * sum_m X[m,i] * Cb[m,j]
//   new_w[i,j] = plastic[i,j] + pf * hebb[i,j]      (pf = rate[0]*strength)
//   accumulate sum(new_w^2) into g_sumsq
// ---------------------------------------------------------------------------
__global__ __launch_bounds__(256, 2)
void gemm2_tn(const float* __restrict__ X,       // [MTOT, HDIM]
              const float* __restrict__ Cb,      // combined [MTOT, HDIM]
              const float* __restrict__ plastic, // [HDIM, HDIM]
              const float* __restrict__ prate,   // [1]
              const float* __restrict__ hstr,    // [1]
              float* __restrict__ Wout) {
    __shared__ float As[16][132];   // [m_local][i] direct layout
    __shared__ float Bs[16][132];   // [m_local][j]

    const int tid = threadIdx.x;
    const int tx = tid & 15;
    const int ty = tid >> 4;
    const int i0 = blockIdx.y * 128;
    const int j0 = blockIdx.x * 128;

    float acc[8][8];
    #pragma unroll
    for (int i = 0; i < 8; i++)
        #pragma unroll
        for (int j = 0; j < 8; j++) acc[i][j] = 0.0f;

    for (int k0 = 0; k0 < MTOT; k0 += 16) {
        #pragma unroll
        for (int s = 0; s < 2; s++) {
            int slot = tid + s * 256;   // 0..511
            int mrow = slot >> 5;       // 0..15
            int iq   = slot & 31;       // 0..31 float4 slots
            float4 v = *reinterpret_cast<const float4*>(
                &X[(size_t)(k0 + mrow) * HDIM + i0 + iq * 4]);
            *reinterpret_cast<float4*>(&As[mrow][iq * 4]) = v;
        }
        #pragma unroll
        for (int s = 0; s < 2; s++) {
            int slot = tid + s * 256;
            int mrow = slot >> 5;
            int jq   = slot & 31;
            float4 v = *reinterpret_cast<const float4*>(
                &Cb[(size_t)(k0 + mrow) * HDIM + j0 + jq * 4]);
            *reinterpret_cast<float4*>(&Bs[mrow][jq * 4]) = v;
        }
        __syncthreads();

        #pragma unroll
        for (int kk = 0; kk < 16; kk++) {
            float a[8], b[8];
            *reinterpret_cast<float4*>(&a[0]) =
                *reinterpret_cast<const float4*>(&As[kk][ty * 8]);
            *reinterpret_cast<float4*>(&a[4]) =
                *reinterpret_cast<const float4*>(&As[kk][ty * 8 + 4]);
            *reinterpret_cast<float4*>(&b[0]) =
                *reinterpret_cast<const float4*>(&Bs[kk][tx * 8]);
            *reinterpret_cast<float4*>(&b[4]) =
                *reinterpret_cast<const float4*>(&Bs[kk][tx * 8 + 4]);
            #pragma unroll
            for (int i = 0; i < 8; i++)
                #pragma unroll
                for (int j = 0; j < 8; j++)
                    acc[i][j] += a[i] * b[j];
        }
        __syncthreads();
    }

    // Fused epilogue: new_w = plastic + pf * hebb, accumulate sumsq
    const float pf = prate[0] * hstr[0];
    const float invM = 1.0f / (float)MTOT;
    float local = 0.0f;
    #pragma unroll
    for (int i = 0; i < 8; i++) {
        int ii = i0 + ty * 8 + i;
        #pragma unroll
        for (int j = 0; j < 8; j += 4) {
            int jj = j0 + tx * 8 + j;
            float4 p = *reinterpret_cast<const float4*>(
                &plastic[(size_t)ii * HDIM + jj]);
            float4 w;
            w.x = p.x + pf * (acc[i][j + 0] * invM);
            w.y = p.y + pf * (acc[i][j + 1] * invM);
            w.z = p.z + pf * (acc[i][j + 2] * invM);
            w.w = p.w + pf * (acc[i][j + 3] * invM);
            *reinterpret_cast<float4*>(&Wout[(size_t)ii * HDIM + jj]) = w;
            local += w.x * w.x + w.y * w.y + w.z * w.z + w.w * w.w;
        }
    }

    // Block reduce into g_sumsq (reuse As smem)
    float* red = &As[0][0];
    red[tid] = local;
    __syncthreads();
    #pragma unroll
    for (int s = 128; s > 0; s >>= 1) {
        if (tid < s) red[tid] += red[tid + s];
        __syncthreads();
    }
    if (tid == 0) atomicAdd(&g_sumsq, red[0]);
}

// ---------------------------------------------------------------------------
// Launch
// ---------------------------------------------------------------------------
extern "C" void kernel_launch(void* const* d_in, const int* in_sizes, int n_in,
                              void* d_out, int out_size) {
    const float* x       = (const float*)d_in[0];  // [8,2048,2048]
    const float* plastic = (const float*)d_in[1];  // [2048,2048]
    const float* prate   = (const float*)d_in[2];  // [1]
    const float* fixed_w = (const float*)d_in[3];  // [2048,2048]
    const float* fixed_b = (const float*)d_in[4];  // [2048]
    const float* hstr    = (const float*)d_in[5];  // scalar

    float* combined = (float*)d_out;                      // [16384,2048]
    float* new_w    = (float*)d_out + COMBINED_ELEMS;     // [2048,2048]

    // 1) reset norm accumulator
    zero_acc_kernel<<<1, 1>>>();

    // 2) W_sum = fixed_w + plastic
    wsum_kernel<<<W_ELEMS / 4 / 256, 256>>>(fixed_w, plastic);

    // 3) combined = x @ W_sumT + b
    {
        dim3 grid(HDIM / 128, MTOT / 128);   // (16, 128)
        gemm1_nt<<<grid, 256>>>(x, fixed_b, combined);
    }

    // 4) new_w (unnormalized) + sumsq
    {
        dim3 grid(HDIM / 128, HDIM / 128);   // (16, 16)
        gemm2_tn<<<grid, 256>>>(x, combined, plastic, prate, hstr, new_w);
    }

    // 5) conditional normalization
    scale_w_kernel<<<W_ELEMS / 4 / 256, 256>>>(new_w);
}

// round 5
// speedup vs baseline: 3.1357x; 3.1357x over previous
#include <cuda_runtime.h>
#include <cstdint>

#define HDIM 2048
#define MTOT 16384
#define COMBINED_ELEMS (MTOT * HDIM)
#define W_ELEMS (HDIM * HDIM)

__device__ __align__(256) float g_wsum[W_ELEMS];
__device__ float g_sumsq;

// ---------------------------------------------------------------------------
// Helpers (baseline sm_80+ ISA only — no arch-specific instructions)
// ---------------------------------------------------------------------------
__device__ __forceinline__ uint32_t f2tf32(float f) {
    uint32_t r;
    asm("cvt.rna.tf32.f32 %0, %1;" : "=r"(r) : "f"(f));
    return r;
}

__device__ __forceinline__ void mma_tf32(float* d, const uint32_t* a, const uint32_t* b) {
    asm volatile(
        "mma.sync.aligned.m16n8k8.row.col.f32.tf32.tf32.f32 "
        "{%0,%1,%2,%3}, {%4,%5,%6,%7}, {%8,%9}, {%0,%1,%2,%3};"
        : "+f"(d[0]), "+f"(d[1]), "+f"(d[2]), "+f"(d[3])
        : "r"(a[0]), "r"(a[1]), "r"(a[2]), "r"(a[3]), "r"(b[0]), "r"(b[1]));
}

__device__ __forceinline__ uint4 cvt4(float4 v) {
    return make_uint4(f2tf32(v.x), f2tf32(v.y), f2tf32(v.z), f2tf32(v.w));
}

// ---------------------------------------------------------------------------
// Small kernels
// ---------------------------------------------------------------------------
__global__ void zero_acc_kernel() { g_sumsq = 0.0f; }

__global__ void wsum_kernel(const float* __restrict__ fw,
                            const float* __restrict__ pw) {
    int i = (blockIdx.x * blockDim.x + threadIdx.x) * 4;
    float4 a = *reinterpret_cast<const float4*>(&fw[i]);
    float4 b = *reinterpret_cast<const float4*>(&pw[i]);
    float4 o; o.x = a.x + b.x; o.y = a.y + b.y; o.z = a.z + b.z; o.w = a.w + b.w;
    *reinterpret_cast<float4*>(&g_wsum[i]) = o;
}

__global__ void scale_w_kernel(float* __restrict__ W) {
    float n = sqrtf(g_sumsq);
    float s = (n > 1.0f) ? (1.0f / n) : 1.0f;
    int i = (blockIdx.x * blockDim.x + threadIdx.x) * 4;
    float4 v = *reinterpret_cast<float4*>(&W[i]);
    v.x *= s; v.y *= s; v.z *= s; v.w *= s;
    *reinterpret_cast<float4*>(&W[i]) = v;
}

// ---------------------------------------------------------------------------
// GEMM1 (NT, tf32 mma.sync): C[m,n] = sum_k x[m,k]*wsum[n,k] + bias[n]
// Tile 128x128, KCHUNK=16, 2-stage. 8 warps = 4(m) x 2(n), warp tile 32x64.
// SMEM layout [row][k], row stride 20 (fragment LDS conflict-free).
// ---------------------------------------------------------------------------
#define S1 20
#define KCH 16

__global__ __launch_bounds__(256, 2)
void gemm1_mma(const float* __restrict__ A,     // x [MTOT][HDIM]
               const float* __restrict__ bias,
               float* __restrict__ C) {
    __shared__ uint32_t As[2][128 * S1];
    __shared__ uint32_t Bs[2][128 * S1];

    const int tid = threadIdx.x;
    const int wid = tid >> 5;
    const int lid = tid & 31;
    const int wm = wid & 3;          // 0..3 -> m offset
    const int wn = wid >> 2;         // 0..1 -> n offset
    const int r = lid >> 2;
    const int cq = lid & 3;
    const int m0 = blockIdx.y * 128;
    const int n0 = blockIdx.x * 128;
    const int K = HDIM;

    // staging slot mapping: row = slot>>2 (coalesced 64B/row), kq = slot&3
    const int srow = tid >> 2;       // slot i: row = srow + i*64
    const int skq  = tid & 3;

    float acc[2][8][4];
    #pragma unroll
    for (int i = 0; i < 2; i++)
        #pragma unroll
        for (int t = 0; t < 8; t++)
            #pragma unroll
            for (int q = 0; q < 4; q++) acc[i][t][q] = 0.0f;

    const int nchunk = K / KCH;

    // stage chunk 0
    {
        #pragma unroll
        for (int i = 0; i < 2; i++) {
            int row = srow + i * 64;
            float4 va = *reinterpret_cast<const float4*>(&A[(size_t)(m0 + row) * K + skq * 4]);
            float4 vb = *reinterpret_cast<const float4*>(&g_wsum[(size_t)(n0 + row) * K + skq * 4]);
            *reinterpret_cast<uint4*>(&As[0][row * S1 + skq * 4]) = cvt4(va);
            *reinterpret_cast<uint4*>(&Bs[0][row * S1 + skq * 4]) = cvt4(vb);
        }
    }
    __syncthreads();

    for (int c = 0; c < nchunk; c++) {
        const int st = c & 1;
        float4 pa[2], pb[2];
        if (c + 1 < nchunk) {
            int k0 = (c + 1) * KCH;
            #pragma unroll
            for (int i = 0; i < 2; i++) {
                int row = srow + i * 64;
                pa[i] = *reinterpret_cast<const float4*>(&A[(size_t)(m0 + row) * K + k0 + skq * 4]);
                pb[i] = *reinterpret_cast<const float4*>(&g_wsum[(size_t)(n0 + row) * K + k0 + skq * 4]);
            }
        }

        #pragma unroll
        for (int ks = 0; ks < 2; ks++) {
            const int cb = ks * 8 + cq;
            uint32_t a[2][4];
            #pragma unroll
            for (int i = 0; i < 2; i++) {
                int rr = wm * 32 + 16 * i + r;
                a[i][0] = As[st][rr * S1 + cb];
                a[i][1] = As[st][(rr + 8) * S1 + cb];
                a[i][2] = As[st][rr * S1 + cb + 4];
                a[i][3] = As[st][(rr + 8) * S1 + cb + 4];
            }
            #pragma unroll
            for (int t = 0; t < 8; t++) {
                int nn = wn * 64 + 8 * t + r;
                uint32_t b[2];
                b[0] = Bs[st][nn * S1 + cb];
                b[1] = Bs[st][nn * S1 + cb + 4];
                mma_tf32(acc[0][t], a[0], b);
                mma_tf32(acc[1][t], a[1], b);
            }
        }

        if (c + 1 < nchunk) {
            #pragma unroll
            for (int i = 0; i < 2; i++) {
                int row = srow + i * 64;
                *reinterpret_cast<uint4*>(&As[st ^ 1][row * S1 + skq * 4]) = cvt4(pa[i]);
                *reinterpret_cast<uint4*>(&Bs[st ^ 1][row * S1 + skq * 4]) = cvt4(pb[i]);
            }
        }
        __syncthreads();
    }

    // epilogue: + bias, write C
    #pragma unroll
    for (int i = 0; i < 2; i++) {
        int row = m0 + wm * 32 + 16 * i + r;
        #pragma unroll
        for (int t = 0; t < 8; t++) {
            int col = n0 + wn * 64 + 8 * t + 2 * cq;
            float2 bv = *reinterpret_cast<const float2*>(&bias[col]);
            float2 o0, o1;
            o0.x = acc[i][t][0] + bv.x; o0.y = acc[i][t][1] + bv.y;
            o1.x = acc[i][t][2] + bv.x; o1.y = acc[i][t][3] + bv.y;
            *reinterpret_cast<float2*>(&C[(size_t)row * HDIM + col]) = o0;
            *reinterpret_cast<float2*>(&C[(size_t)(row + 8) * HDIM + col]) = o1;
        }
    }
}

// ---------------------------------------------------------------------------
// GEMM2 (TN, tf32 mma.sync):
//   hebb[i,j] = sum_m X[m,i] * Cb[m,j];  new_w = plastic + pf/M * hebb; sumsq
// Tile 128x128 over (i,j), reduction m, KCHUNK=16.
// SMEM layout [m][col], stride 136 (staging direct+coalesced; frag LDS
// banks = 8c + r, conflict-free).
// ---------------------------------------------------------------------------
#define S2 136

__global__ __launch_bounds__(256, 2)
void gemm2_mma(const float* __restrict__ X,        // [MTOT][HDIM]
               const float* __restrict__ Cb,       // [MTOT][HDIM]
               const float* __restrict__ plastic,
               const float* __restrict__ prate,
               const float* __restrict__ hstr,
               float* __restrict__ Wout) {
    __shared__ uint32_t As[2][KCH * S2];
    __shared__ uint32_t Bs[2][KCH * S2];

    const int tid = threadIdx.x;
    const int wid = tid >> 5;
    const int lid = tid & 31;
    const int wm = wid & 3;
    const int wn = wid >> 2;
    const int r = lid >> 2;
    const int cq = lid & 3;
    const int i0 = blockIdx.y * 128;
    const int j0 = blockIdx.x * 128;

    // staging: slot = tid + 256*it ; mrow = slot>>5 (0..15), iq = slot&31
    const int smrow = tid >> 5;      // + 8*it
    const int siq   = tid & 31;

    float acc[2][8][4];
    #pragma unroll
    for (int i = 0; i < 2; i++)
        #pragma unroll
        for (int t = 0; t < 8; t++)
            #pragma unroll
            for (int q = 0; q < 4; q++) acc[i][t][q] = 0.0f;

    const int nchunk = MTOT / KCH;

    {
        #pragma unroll
        for (int it = 0; it < 2; it++) {
            int mr = smrow + it * 8;
            float4 va = *reinterpret_cast<const float4*>(&X[(size_t)mr * HDIM + i0 + siq * 4]);
            float4 vb = *reinterpret_cast<const float4*>(&Cb[(size_t)mr * HDIM + j0 + siq * 4]);
            *reinterpret_cast<uint4*>(&As[0][mr * S2 + siq * 4]) = cvt4(va);
            *reinterpret_cast<uint4*>(&Bs[0][mr * S2 + siq * 4]) = cvt4(vb);
        }
    }
    __syncthreads();

    for (int c = 0; c < nchunk; c++) {
        const int st = c & 1;
        float4 pa[2], pb[2];
        if (c + 1 < nchunk) {
            int m0g = (c + 1) * KCH;
            #pragma unroll
            for (int it = 0; it < 2; it++) {
                int mr = smrow + it * 8;
                pa[it] = *reinterpret_cast<const float4*>(&X[(size_t)(m0g + mr) * HDIM + i0 + siq * 4]);
                pb[it] = *reinterpret_cast<const float4*>(&Cb[(size_t)(m0g + mr) * HDIM + j0 + siq * 4]);
            }
        }

        #pragma unroll
        for (int ks = 0; ks < 2; ks++) {
            const int cb = ks * 8 + cq;
            uint32_t a[2][4];
            #pragma unroll
            for (int i = 0; i < 2; i++) {
                int ii = wm * 32 + 16 * i + r;
                a[i][0] = As[st][cb * S2 + ii];
                a[i][1] = As[st][cb * S2 + ii + 8];
                a[i][2] = As[st][(cb + 4) * S2 + ii];
                a[i][3] = As[st][(cb + 4) * S2 + ii + 8];
            }
            #pragma unroll
            for (int t = 0; t < 8; t++) {
                int jj = wn * 64 + 8 * t + r;
                uint32_t b[2];
                b[0] = Bs[st][cb * S2 + jj];
                b[1] = Bs[st][(cb + 4) * S2 + jj];
                mma_tf32(acc[0][t], a[0], b);
                mma_tf32(acc[1][t], a[1], b);
            }
        }

        if (c + 1 < nchunk) {
            #pragma unroll
            for (int it = 0; it < 2; it++) {
                int mr = smrow + it * 8;
                *reinterpret_cast<uint4*>(&As[st ^ 1][mr * S2 + siq * 4]) = cvt4(pa[it]);
                *reinterpret_cast<uint4*>(&Bs[st ^ 1][mr * S2 + siq * 4]) = cvt4(pb[it]);
            }
        }
        __syncthreads();
    }

    // epilogue
    const float pf = __ldg(&prate[0]) * __ldg(&hstr[0]) * (1.0f / (float)MTOT);
    float ss = 0.0f;
    #pragma unroll
    for (int i = 0; i < 2; i++) {
        int row = i0 + wm * 32 + 16 * i + r;
        #pragma unroll
        for (int t = 0; t < 8; t++) {
            int col = j0 + wn * 64 + 8 * t + 2 * cq;
            size_t b0 = (size_t)row * HDIM + col;
            size_t b1 = (size_t)(row + 8) * HDIM + col;
            float2 p0 = *reinterpret_cast<const float2*>(&plastic[b0]);
            float2 p1 = *reinterpret_cast<const float2*>(&plastic[b1]);
            float2 o0, o1;
            o0.x = p0.x + pf * acc[i][t][0]; o0.y = p0.y + pf * acc[i][t][1];
            o1.x = p1.x + pf * acc[i][t][2]; o1.y = p1.y + pf * acc[i][t][3];
            *reinterpret_cast<float2*>(&Wout[b0]) = o0;
            *reinterpret_cast<float2*>(&Wout[b1]) = o1;
            ss += o0.x * o0.x + o0.y * o0.y + o1.x * o1.x + o1.y * o1.y;
        }
    }
    // warp reduce + atomic
    #pragma unroll
    for (int s = 16; s > 0; s >>= 1)
        ss += __shfl_xor_sync(0xFFFFFFFFu, ss, s);
    if (lid == 0) atomicAdd(&g_sumsq, ss);
}

// ---------------------------------------------------------------------------
// Launch
// ---------------------------------------------------------------------------
extern "C" void kernel_launch(void* const* d_in, const int* in_sizes, int n_in,
                              void* d_out, int out_size) {
    const float* x       = (const float*)d_in[0];
    const float* plastic = (const float*)d_in[1];
    const float* prate   = (const float*)d_in[2];
    const float* fixed_w = (const float*)d_in[3];
    const float* fixed_b = (const float*)d_in[4];
    const float* hstr    = (const float*)d_in[5];

    float* combined = (float*)d_out;
    float* new_w    = (float*)d_out + COMBINED_ELEMS;

    zero_acc_kernel<<<1, 1>>>();
    wsum_kernel<<<W_ELEMS / 4 / 256, 256>>>(fixed_w, plastic);

    gemm1_mma<<<dim3(HDIM / 128, MTOT / 128), 256>>>(x, fixed_b, combined);

    gemm2_mma<<<dim3(HDIM / 128, HDIM / 128), 256>>>(
        x, combined, plastic, prate, hstr, new_w);

    scale_w_kernel<<<W_ELEMS / 4 / 256, 256>>>(new_w);
}

// round 8
// speedup vs baseline: 3.3776x; 1.0772x over previous
#include <cuda_runtime.h>
#include <cstdint>

#define HDIM 2048
#define MTOT 16384
#define COMBINED_ELEMS (MTOT * HDIM)
#define W_ELEMS (HDIM * HDIM)

// Scratch (static __device__ — no allocation allowed)
__device__ __align__(256) uint32_t g_xtf[MTOT * HDIM];   // x as tf32 bits
__device__ __align__(256) uint32_t g_wtf[W_ELEMS];       // (fixed+plastic) as tf32
__device__ __align__(256) uint32_t g_ctf[MTOT * HDIM];   // combined as tf32
__device__ float g_sumsq;

// ---------------------------------------------------------------------------
// Helpers (baseline sm_80+ ISA only)
// ---------------------------------------------------------------------------
__device__ __forceinline__ uint32_t f2tf32(float f) {
    uint32_t r;
    asm("cvt.rna.tf32.f32 %0, %1;" : "=r"(r) : "f"(f));
    return r;
}

__device__ __forceinline__ void mma_tf32(float* d, const uint32_t* a, const uint32_t* b) {
    asm volatile(
        "mma.sync.aligned.m16n8k8.row.col.f32.tf32.tf32.f32 "
        "{%0,%1,%2,%3}, {%4,%5,%6,%7}, {%8,%9}, {%0,%1,%2,%3};"
        : "+f"(d[0]), "+f"(d[1]), "+f"(d[2]), "+f"(d[3])
        : "r"(a[0]), "r"(a[1]), "r"(a[2]), "r"(a[3]), "r"(b[0]), "r"(b[1]));
}

__device__ __forceinline__ void cp16(uint32_t smem_addr, const void* gptr) {
    asm volatile("cp.async.cg.shared.global [%0], [%1], 16;"
                 :: "r"(smem_addr), "l"(gptr) : "memory");
}
__device__ __forceinline__ void cp_commit() {
    asm volatile("cp.async.commit_group;" ::: "memory");
}
__device__ __forceinline__ void cp_wait1() {
    asm volatile("cp.async.wait_group 1;" ::: "memory");
}
__device__ __forceinline__ void cp_wait0() {
    asm volatile("cp.async.wait_group 0;" ::: "memory");
}

// ---------------------------------------------------------------------------
// Small kernels
// ---------------------------------------------------------------------------
__global__ void zero_acc_kernel() { g_sumsq = 0.0f; }

// wsum_tf = tf32(fixed + plastic)
__global__ void wsumtf_kernel(const float* __restrict__ fw,
                              const float* __restrict__ pw) {
    int i = (blockIdx.x * blockDim.x + threadIdx.x) * 4;
    float4 a = *reinterpret_cast<const float4*>(&fw[i]);
    float4 b = *reinterpret_cast<const float4*>(&pw[i]);
    uint4 o = make_uint4(f2tf32(a.x + b.x), f2tf32(a.y + b.y),
                         f2tf32(a.z + b.z), f2tf32(a.w + b.w));
    *reinterpret_cast<uint4*>(&g_wtf[i]) = o;
}

// x_tf = tf32(x)
__global__ void xtf_kernel(const float* __restrict__ X) {
    size_t i = ((size_t)blockIdx.x * blockDim.x + threadIdx.x) * 4;
    float4 v = *reinterpret_cast<const float4*>(&X[i]);
    *reinterpret_cast<uint4*>(&g_xtf[i]) =
        make_uint4(f2tf32(v.x), f2tf32(v.y), f2tf32(v.z), f2tf32(v.w));
}

__global__ void scale_w_kernel(float* __restrict__ W) {
    float n = sqrtf(g_sumsq);
    float s = (n > 1.0f) ? (1.0f / n) : 1.0f;
    int i = (blockIdx.x * blockDim.x + threadIdx.x) * 4;
    float4 v = *reinterpret_cast<float4*>(&W[i]);
    v.x *= s; v.y *= s; v.z *= s; v.w *= s;
    *reinterpret_cast<float4*>(&W[i]) = v;
}

// ---------------------------------------------------------------------------
// GEMM1 (NT): C[m,n] = sum_k x[m,k]*wsum[n,k] + bias[n]; also emit tf32 copy.
// 128x128 tile, KCH=32, 3-stage cp.async. 8 warps = 4(m) x 2(n), warp 32x64.
// SMEM [row][k], row stride 36 u32 (fragment LDS conflict-free: 4r+cq).
// ---------------------------------------------------------------------------
#define KCH 32
#define S1 36
#define G1_MAT (128 * S1)            // u32 per matrix per stage
#define G1_STAGE (2 * G1_MAT)        // u32 per stage
#define G1_SMEM_BYTES (3 * G1_STAGE * 4)   // 110592 B

__global__ __launch_bounds__(256, 2)
void gemm1_mma(const float* __restrict__ bias,
               float* __restrict__ C) {
    extern __shared__ uint32_t sh[];
    const uint32_t shb = (uint32_t)__cvta_generic_to_shared(sh);

    const int tid = threadIdx.x;
    const int wid = tid >> 5;
    const int lid = tid & 31;
    const int wm = wid & 3;
    const int wn = wid >> 2;
    const int r = lid >> 2;
    const int cq = lid & 3;
    const int m0 = blockIdx.y * 128;
    const int n0 = blockIdx.x * 128;
    const int nchunk = HDIM / KCH;   // 64

    float acc[2][8][4];
    #pragma unroll
    for (int i = 0; i < 2; i++)
        #pragma unroll
        for (int t = 0; t < 8; t++)
            #pragma unroll
            for (int q = 0; q < 4; q++) acc[i][t][q] = 0.0f;

    // cp.async staging: slot = tid + 256*i; row = slot>>3, kq = slot&7
    auto issue = [&](int c) {
        const int s = c % 3;
        const uint32_t sa = shb + (uint32_t)(s * G1_STAGE) * 4;
        const uint32_t sb = sa + (uint32_t)G1_MAT * 4;
        const int k0 = c * KCH;
        #pragma unroll
        for (int i = 0; i < 4; i++) {
            int slot = tid + (i << 8);
            int row = slot >> 3, kq = slot & 7;
            cp16(sa + (uint32_t)(row * S1 + kq * 4) * 4,
                 &g_xtf[(size_t)(m0 + row) * HDIM + k0 + kq * 4]);
            cp16(sb + (uint32_t)(row * S1 + kq * 4) * 4,
                 &g_wtf[(size_t)(n0 + row) * HDIM + k0 + kq * 4]);
        }
        cp_commit();
    };

    issue(0);
    issue(1);

    for (int c = 0; c < nchunk; c++) {
        if (c == nchunk - 1) cp_wait0(); else cp_wait1();
        __syncthreads();
        if (c + 2 < nchunk) issue(c + 2);

        const uint32_t* As = sh + (c % 3) * G1_STAGE;
        const uint32_t* Bs = As + G1_MAT;
        #pragma unroll
        for (int ks = 0; ks < 4; ks++) {
            const int cb = ks * 8 + cq;
            uint32_t a[2][4];
            #pragma unroll
            for (int i = 0; i < 2; i++) {
                int rr = wm * 32 + 16 * i + r;
                a[i][0] = As[rr * S1 + cb];
                a[i][1] = As[(rr + 8) * S1 + cb];
                a[i][2] = As[rr * S1 + cb + 4];
                a[i][3] = As[(rr + 8) * S1 + cb + 4];
            }
            #pragma unroll
            for (int t = 0; t < 8; t++) {
                int nn = wn * 64 + 8 * t + r;
                uint32_t b[2];
                b[0] = Bs[nn * S1 + cb];
                b[1] = Bs[nn * S1 + cb + 4];
                mma_tf32(acc[0][t], a[0], b);
                mma_tf32(acc[1][t], a[1], b);
            }
        }
        __syncthreads();
    }

    // epilogue: + bias -> C (fp32) and g_ctf (tf32)
    #pragma unroll
    for (int i = 0; i < 2; i++) {
        int row = m0 + wm * 32 + 16 * i + r;
        #pragma unroll
        for (int t = 0; t < 8; t++) {
            int col = n0 + wn * 64 + 8 * t + 2 * cq;
            float2 bv = *reinterpret_cast<const float2*>(&bias[col]);
            float2 o0, o1;
            o0.x = acc[i][t][0] + bv.x; o0.y = acc[i][t][1] + bv.y;
            o1.x = acc[i][t][2] + bv.x; o1.y = acc[i][t][3] + bv.y;
            size_t b0 = (size_t)row * HDIM + col;
            size_t b1 = (size_t)(row + 8) * HDIM + col;
            *reinterpret_cast<float2*>(&C[b0]) = o0;
            *reinterpret_cast<float2*>(&C[b1]) = o1;
            *reinterpret_cast<uint2*>(&g_ctf[b0]) =
                make_uint2(f2tf32(o0.x), f2tf32(o0.y));
            *reinterpret_cast<uint2*>(&g_ctf[b1]) =
                make_uint2(f2tf32(o1.x), f2tf32(o1.y));
        }
    }
}

// ---------------------------------------------------------------------------
// GEMM2 (TN): hebb[i,j] = sum_m x[m,i]*combined[m,j];
//             new_w = plastic + pf/M * hebb; accumulate sumsq.
// 128x128 tile over (i,j), reduction m, KCH=32, 3-stage cp.async.
// SMEM [m][col], stride 136 u32 (frag banks 8c+r, conflict-free).
// ---------------------------------------------------------------------------
#define S2 136
#define G2_MAT (KCH * S2)            // 4352 u32
#define G2_STAGE (2 * G2_MAT)
#define G2_SMEM_BYTES (3 * G2_STAGE * 4)   // 104448 B

__global__ __launch_bounds__(256, 2)
void gemm2_mma(const float* __restrict__ plastic,
               const float* __restrict__ prate,
               const float* __restrict__ hstr,
               float* __restrict__ Wout) {
    extern __shared__ uint32_t sh[];
    const uint32_t shb = (uint32_t)__cvta_generic_to_shared(sh);

    const int tid = threadIdx.x;
    const int wid = tid >> 5;
    const int lid = tid & 31;
    const int wm = wid & 3;
    const int wn = wid >> 2;
    const int r = lid >> 2;
    const int cq = lid & 3;
    const int i0 = blockIdx.y * 128;
    const int j0 = blockIdx.x * 128;
    const int nchunk = MTOT / KCH;   // 512

    float acc[2][8][4];
    #pragma unroll
    for (int i = 0; i < 2; i++)
        #pragma unroll
        for (int t = 0; t < 8; t++)
            #pragma unroll
            for (int q = 0; q < 4; q++) acc[i][t][q] = 0.0f;

    // staging: slot = tid + 256*i; mrow = slot>>5 (0..31), iq = slot&31
    auto issue = [&](int c) {
        const int s = c % 3;
        const uint32_t sa = shb + (uint32_t)(s * G2_STAGE) * 4;
        const uint32_t sb = sa + (uint32_t)G2_MAT * 4;
        const int mg = c * KCH;
        #pragma unroll
        for (int i = 0; i < 4; i++) {
            int slot = tid + (i << 8);
            int mrow = slot >> 5, iq = slot & 31;
            cp16(sa + (uint32_t)(mrow * S2 + iq * 4) * 4,
                 &g_xtf[(size_t)(mg + mrow) * HDIM + i0 + iq * 4]);
            cp16(sb + (uint32_t)(mrow * S2 + iq * 4) * 4,
                 &g_ctf[(size_t)(mg + mrow) * HDIM + j0 + iq * 4]);
        }
        cp_commit();
    };

    issue(0);
    issue(1);

    for (int c = 0; c < nchunk; c++) {
        if (c == nchunk - 1) cp_wait0(); else cp_wait1();
        __syncthreads();
        if (c + 2 < nchunk) issue(c + 2);

        const uint32_t* As = sh + (c % 3) * G2_STAGE;
        const uint32_t* Bs = As + G2_MAT;
        #pragma unroll
        for (int ks = 0; ks < 4; ks++) {
            const int cb = ks * 8 + cq;
            uint32_t a[2][4];
            #pragma unroll
            for (int i = 0; i < 2; i++) {
                int ii = wm * 32 + 16 * i + r;
                a[i][0] = As[cb * S2 + ii];
                a[i][1] = As[cb * S2 + ii + 8];
                a[i][2] = As[(cb + 4) * S2 + ii];
                a[i][3] = As[(cb + 4) * S2 + ii + 8];
            }
            #pragma unroll
            for (int t = 0; t < 8; t++) {
                int jj = wn * 64 + 8 * t + r;
                uint32_t b[2];
                b[0] = Bs[cb * S2 + jj];
                b[1] = Bs[(cb + 4) * S2 + jj];
                mma_tf32(acc[0][t], a[0], b);
                mma_tf32(acc[1][t], a[1], b);
            }
        }
        __syncthreads();
    }

    // epilogue
    const float pf = __ldg(&prate[0]) * __ldg(&hstr[0]) * (1.0f / (float)MTOT);
    float ss = 0.0f;
    #pragma unroll
    for (int i = 0; i < 2; i++) {
        int row = i0 + wm * 32 + 16 * i + r;
        #pragma unroll
        for (int t = 0; t < 8; t++) {
            int col = j0 + wn * 64 + 8 * t + 2 * cq;
            size_t b0 = (size_t)row * HDIM + col;
            size_t b1 = (size_t)(row + 8) * HDIM + col;
            float2 p0 = *reinterpret_cast<const float2*>(&plastic[b0]);
            float2 p1 = *reinterpret_cast<const float2*>(&plastic[b1]);
            float2 o0, o1;
            o0.x = p0.x + pf * acc[i][t][0]; o0.y = p0.y + pf * acc[i][t][1];
            o1.x = p1.x + pf * acc[i][t][2]; o1.y = p1.y + pf * acc[i][t][3];
            *reinterpret_cast<float2*>(&Wout[b0]) = o0;
            *reinterpret_cast<float2*>(&Wout[b1]) = o1;
            ss += o0.x * o0.x + o0.y * o0.y + o1.x * o1.x + o1.y * o1.y;
        }
    }
    #pragma unroll
    for (int s = 16; s > 0; s >>= 1)
        ss += __shfl_xor_sync(0xFFFFFFFFu, ss, s);
    if (lid == 0) atomicAdd(&g_sumsq, ss);
}

// ---------------------------------------------------------------------------
// Launch
// ---------------------------------------------------------------------------
extern "C" void kernel_launch(void* const* d_in, const int* in_sizes, int n_in,
                              void* d_out, int out_size) {
    const float* x       = (const float*)d_in[0];
    const float* plastic = (const float*)d_in[1];
    const float* prate   = (const float*)d_in[2];
    const float* fixed_w = (const float*)d_in[3];
    const float* fixed_b = (const float*)d_in[4];
    const float* hstr    = (const float*)d_in[5];

    float* combined = (float*)d_out;
    float* new_w    = (float*)d_out + COMBINED_ELEMS;

    static bool attr_done = false;
    if (!attr_done) {
        cudaFuncSetAttribute(gemm1_mma,
            cudaFuncAttributeMaxDynamicSharedMemorySize, G1_SMEM_BYTES);
        cudaFuncSetAttribute(gemm2_mma,
            cudaFuncAttributeMaxDynamicSharedMemorySize, G2_SMEM_BYTES);
        attr_done = true;
    }

    zero_acc_kernel<<<1, 1>>>();
    wsumtf_kernel<<<W_ELEMS / 4 / 256, 256>>>(fixed_w, plastic);
    xtf_kernel<<<COMBINED_ELEMS / 4 / 256, 256>>>(x);

    gemm1_mma<<<dim3(HDIM / 128, MTOT / 128), 256, G1_SMEM_BYTES>>>(
        fixed_b, combined);

    gemm2_mma<<<dim3(HDIM / 128, HDIM / 128), 256, G2_SMEM_BYTES>>>(
        plastic, prate, hstr, new_w);

    scale_w_kernel<<<W_ELEMS / 4 / 256, 256>>>(new_w);
}

// round 9
// speedup vs baseline: 3.5911x; 1.0632x over previous
#include <cuda_runtime.h>
#include <cstdint>

#define HDIM 2048
#define MTOT 16384
#define COMBINED_ELEMS (MTOT * HDIM)
#define W_ELEMS (HDIM * HDIM)

// Scratch (static __device__ — no allocation allowed)
__device__ __align__(256) uint32_t g_xtf[MTOT * HDIM];    // x tf32, [m][h]
__device__ __align__(256) uint32_t g_xtfT[HDIM * MTOT];   // x tf32, [h][m]
__device__ __align__(256) uint32_t g_wtf[W_ELEMS];        // fixed+plastic tf32, [n][k]
__device__ __align__(256) uint32_t g_ctfT[HDIM * MTOT];   // combined tf32, [n][m]
__device__ float g_sumsq;

// ---------------------------------------------------------------------------
// Helpers (baseline sm_80+ ISA only)
// ---------------------------------------------------------------------------
__device__ __forceinline__ uint32_t f2tf32(float f) {
    uint32_t r;
    asm("cvt.rna.tf32.f32 %0, %1;" : "=r"(r) : "f"(f));
    return r;
}

__device__ __forceinline__ void mma_tf32(float* d, const uint32_t* a, const uint32_t* b) {
    asm volatile(
        "mma.sync.aligned.m16n8k8.row.col.f32.tf32.tf32.f32 "
        "{%0,%1,%2,%3}, {%4,%5,%6,%7}, {%8,%9}, {%0,%1,%2,%3};"
        : "+f"(d[0]), "+f"(d[1]), "+f"(d[2]), "+f"(d[3])
        : "r"(a[0]), "r"(a[1]), "r"(a[2]), "r"(a[3]), "r"(b[0]), "r"(b[1]));
}

#define LDSM_X4(d, addr) \
    asm volatile("ldmatrix.sync.aligned.m8n8.x4.shared.b16 {%0,%1,%2,%3}, [%4];" \
        : "=r"((d)[0]), "=r"((d)[1]), "=r"((d)[2]), "=r"((d)[3]) : "r"(addr))

__device__ __forceinline__ void cp16(uint32_t smem_addr, const void* gptr) {
    asm volatile("cp.async.cg.shared.global [%0], [%1], 16;"
                 :: "r"(smem_addr), "l"(gptr) : "memory");
}
__device__ __forceinline__ void cp_commit() {
    asm volatile("cp.async.commit_group;" ::: "memory");
}
__device__ __forceinline__ void cp_wait1() {
    asm volatile("cp.async.wait_group 1;" ::: "memory");
}
__device__ __forceinline__ void cp_wait0() {
    asm volatile("cp.async.wait_group 0;" ::: "memory");
}

// ---------------------------------------------------------------------------
// Small kernels
// ---------------------------------------------------------------------------
__global__ void zero_acc_kernel() { g_sumsq = 0.0f; }

// g_wtf = tf32(fixed + plastic)
__global__ void wsumtf_kernel(const float* __restrict__ fw,
                              const float* __restrict__ pw) {
    int i = (blockIdx.x * blockDim.x + threadIdx.x) * 4;
    float4 a = *reinterpret_cast<const float4*>(&fw[i]);
    float4 b = *reinterpret_cast<const float4*>(&pw[i]);
    *reinterpret_cast<uint4*>(&g_wtf[i]) =
        make_uint4(f2tf32(a.x + b.x), f2tf32(a.y + b.y),
                   f2tf32(a.z + b.z), f2tf32(a.w + b.w));
}

// Fused: read x once, write g_xtf [m][h] (straight) and g_xtfT [h][m] (transposed)
__global__ void xcvt_kernel(const float* __restrict__ X) {
    __shared__ uint32_t t[32][33];
    int bx = blockIdx.x * 32;   // h
    int by = blockIdx.y * 32;   // m
    int tx = threadIdx.x, ty = threadIdx.y;
    #pragma unroll
    for (int j = 0; j < 32; j += 8) {
        uint32_t v = f2tf32(X[(size_t)(by + ty + j) * HDIM + bx + tx]);
        t[ty + j][tx] = v;
        g_xtf[(size_t)(by + ty + j) * HDIM + bx + tx] = v;
    }
    __syncthreads();
    #pragma unroll
    for (int j = 0; j < 32; j += 8)
        g_xtfT[(size_t)(bx + ty + j) * MTOT + by + tx] = t[tx][ty + j];
}

__global__ void scale_w_kernel(float* __restrict__ W) {
    float n = sqrtf(g_sumsq);
    float s = (n > 1.0f) ? (1.0f / n) : 1.0f;
    int i = (blockIdx.x * blockDim.x + threadIdx.x) * 4;
    float4 v = *reinterpret_cast<float4*>(&W[i]);
    v.x *= s; v.y *= s; v.z *= s; v.w *= s;
    *reinterpret_cast<float4*>(&W[i]) = v;
}

// ---------------------------------------------------------------------------
// Shared GEMM config: NT, 128x128 tile, KCH=32, 3-stage cp.async, LDSM frags.
// SMEM [row][k], row stride 36 u32 (LDSM 8-row phases conflict-free: 4l+c).
// 8 warps = 4(m) x 2(n), warp tile 32x64.
// ---------------------------------------------------------------------------
#define KCH 32
#define S1 36
#define G_MAT (128 * S1)
#define G_STAGE (2 * G_MAT)
#define G_SMEM_BYTES (3 * G_STAGE * 4)    // 110592 B
#define EPI_STRIDE 132                    // transpose-staging stride

// Mainloop macro body shared by both kernels via a device function.
// Aq/Bq: row-major [row][K] tf32 sources. Computes acc for tile (r0g, c0g).
__device__ __forceinline__ void gemm_mainloop(
    const uint32_t* __restrict__ Aq, const uint32_t* __restrict__ Bq,
    int K, int r0g, int c0g,
    uint32_t* sh, uint32_t shb,
    float acc[2][8][4])
{
    const int tid = threadIdx.x;
    const int lid = tid & 31;
    const int wid = tid >> 5;
    const int wm = wid & 3;
    const int wn = wid >> 2;
    const int nchunk = K / KCH;

    // LDSM per-lane byte offsets (within a stage's A / B matrix region)
    const uint32_t aoff0 =
        (uint32_t)((wm * 32 + ((lid >> 3) & 1) * 8 + (lid & 7)) * S1
                   + ((lid >> 4) & 1) * 4) * 4;
    const uint32_t aoff1 = aoff0 + 16 * S1 * 4;
    const uint32_t boff0 =
        (uint32_t)((wn * 64 + ((lid >> 4) & 1) * 8 + (lid & 7)) * S1
                   + ((lid >> 3) & 1) * 4) * 4;

    // cp.async staging: slot = tid + 256*i; row = slot>>3, kq = slot&7
    const int srow = tid >> 3;
    const int skq  = tid & 7;

    auto issue = [&](int c) {
        const int s = c % 3;
        const uint32_t sa = shb + (uint32_t)(s * G_STAGE) * 4;
        const uint32_t sb = sa + (uint32_t)G_MAT * 4;
        const int k0 = c * KCH;
        #pragma unroll
        for (int i = 0; i < 4; i++) {
            int row = srow + i * 32;
            cp16(sa + (uint32_t)(row * S1 + skq * 4) * 4,
                 &Aq[(size_t)(r0g + row) * K + k0 + skq * 4]);
            cp16(sb + (uint32_t)(row * S1 + skq * 4) * 4,
                 &Bq[(size_t)(c0g + row) * K + k0 + skq * 4]);
        }
        cp_commit();
    };

    issue(0);
    issue(1);

    for (int c = 0; c < nchunk; c++) {
        if (c >= nchunk - 2) cp_wait0(); else cp_wait1();
        __syncthreads();
        if (c + 2 < nchunk) issue(c + 2);

        const uint32_t sa = shb + (uint32_t)((c % 3) * G_STAGE) * 4;
        const uint32_t sb = sa + (uint32_t)G_MAT * 4;
        #pragma unroll
        for (int ks = 0; ks < 4; ks++) {
            uint32_t a0[4], a1[4];
            LDSM_X4(a0, sa + aoff0 + ks * 32);
            LDSM_X4(a1, sa + aoff1 + ks * 32);
            #pragma unroll
            for (int tp = 0; tp < 4; tp++) {
                uint32_t bt[4];
                LDSM_X4(bt, sb + boff0 + (uint32_t)(tp * 16 * S1 * 4) + ks * 32);
                mma_tf32(acc[0][2 * tp],     a0, &bt[0]);
                mma_tf32(acc[1][2 * tp],     a1, &bt[0]);
                mma_tf32(acc[0][2 * tp + 1], a0, &bt[2]);
                mma_tf32(acc[1][2 * tp + 1], a1, &bt[2]);
            }
        }
    }
    __syncthreads();   // all compute done before smem reuse by caller
}

// ---------------------------------------------------------------------------
// GEMM1: C[m,n] = sum_k x[m,k]*wsum[n,k] + bias[n]
//   outputs: combined (fp32, [m][n]) and g_ctfT (tf32, [n][m])
// ---------------------------------------------------------------------------
__global__ __launch_bounds__(256, 2)
void gemm1_mma(const float* __restrict__ bias,
               float* __restrict__ C) {
    extern __shared__ uint32_t sh[];
    const uint32_t shb = (uint32_t)__cvta_generic_to_shared(sh);

    const int tid = threadIdx.x;
    const int wid = tid >> 5;
    const int lid = tid & 31;
    const int wm = wid & 3;
    const int wn = wid >> 2;
    const int r = lid >> 2;
    const int cq = lid & 3;
    const int m0 = blockIdx.y * 128;
    const int n0 = blockIdx.x * 128;

    float acc[2][8][4];
    #pragma unroll
    for (int i = 0; i < 2; i++)
        #pragma unroll
        for (int t = 0; t < 8; t++)
            #pragma unroll
            for (int q = 0; q < 4; q++) acc[i][t][q] = 0.0f;

    gemm_mainloop(g_xtf, g_wtf, HDIM, m0, n0, sh, shb, acc);

    // direct fp32 write + transpose-stage tf32 into smem
    #pragma unroll
    for (int i = 0; i < 2; i++) {
        int rl = wm * 32 + 16 * i + r;
        #pragma unroll
        for (int t = 0; t < 8; t++) {
            int cl = wn * 64 + 8 * t + 2 * cq;
            float2 bv = *reinterpret_cast<const float2*>(&bias[n0 + cl]);
            float o0 = acc[i][t][0] + bv.x, o1 = acc[i][t][1] + bv.y;
            float o2 = acc[i][t][2] + bv.x, o3 = acc[i][t][3] + bv.y;
            size_t b0 = (size_t)(m0 + rl) * HDIM + n0 + cl;
            size_t b1 = (size_t)(m0 + rl + 8) * HDIM + n0 + cl;
            *reinterpret_cast<float2*>(&C[b0]) = make_float2(o0, o1);
            *reinterpret_cast<float2*>(&C[b1]) = make_float2(o2, o3);
            sh[cl * EPI_STRIDE + rl]           = f2tf32(o0);
            sh[(cl + 1) * EPI_STRIDE + rl]     = f2tf32(o1);
            sh[cl * EPI_STRIDE + rl + 8]       = f2tf32(o2);
            sh[(cl + 1) * EPI_STRIDE + rl + 8] = f2tf32(o3);
        }
    }
    __syncthreads();
    // coalesced store of transposed tile to g_ctfT
    #pragma unroll
    for (int it = 0; it < 16; it++) {
        int slot = tid + (it << 8);
        int col = slot >> 5, mq = slot & 31;
        uint4 v = *reinterpret_cast<const uint4*>(&sh[col * EPI_STRIDE + mq * 4]);
        *reinterpret_cast<uint4*>(
            &g_ctfT[(size_t)(n0 + col) * MTOT + m0 + mq * 4]) = v;
    }
}

// ---------------------------------------------------------------------------
// GEMM2: hebb[i,j] = sum_m xT[i,m]*cT[j,m]; new_w = plastic + pf/M*hebb; sumsq
// ---------------------------------------------------------------------------
__global__ __launch_bounds__(256, 2)
void gemm2_mma(const float* __restrict__ plastic,
               const float* __restrict__ prate,
               const float* __restrict__ hstr,
               float* __restrict__ Wout) {
    extern __shared__ uint32_t sh[];
    const uint32_t shb = (uint32_t)__cvta_generic_to_shared(sh);

    const int tid = threadIdx.x;
    const int wid = tid >> 5;
    const int lid = tid & 31;
    const int wm = wid & 3;
    const int wn = wid >> 2;
    const int r = lid >> 2;
    const int cq = lid & 3;
    const int i0 = blockIdx.y * 128;
    const int j0 = blockIdx.x * 128;

    float acc[2][8][4];
    #pragma unroll
    for (int i = 0; i < 2; i++)
        #pragma unroll
        for (int t = 0; t < 8; t++)
            #pragma unroll
            for (int q = 0; q < 4; q++) acc[i][t][q] = 0.0f;

    gemm_mainloop(g_xtfT, g_ctfT, MTOT, i0, j0, sh, shb, acc);

    const float pf = __ldg(&prate[0]) * __ldg(&hstr[0]) * (1.0f / (float)MTOT);
    float ss = 0.0f;
    #pragma unroll
    for (int i = 0; i < 2; i++) {
        int row = i0 + wm * 32 + 16 * i + r;
        #pragma unroll
        for (int t = 0; t < 8; t++) {
            int col = j0 + wn * 64 + 8 * t + 2 * cq;
            size_t b0 = (size_t)row * HDIM + col;
            size_t b1 = (size_t)(row + 8) * HDIM + col;
            float2 p0 = *reinterpret_cast<const float2*>(&plastic[b0]);
            float2 p1 = *reinterpret_cast<const float2*>(&plastic[b1]);
            float2 o0, o1;
            o0.x = p0.x + pf * acc[i][t][0]; o0.y = p0.y + pf * acc[i][t][1];
            o1.x = p1.x + pf * acc[i][t][2]; o1.y = p1.y + pf * acc[i][t][3];
            *reinterpret_cast<float2*>(&Wout[b0]) = o0;
            *reinterpret_cast<float2*>(&Wout[b1]) = o1;
            ss += o0.x * o0.x + o0.y * o0.y + o1.x * o1.x + o1.y * o1.y;
        }
    }
    #pragma unroll
    for (int s = 16; s > 0; s >>= 1)
        ss += __shfl_xor_sync(0xFFFFFFFFu, ss, s);
    if (lid == 0) atomicAdd(&g_sumsq, ss);
}

// ---------------------------------------------------------------------------
// Launch
// ---------------------------------------------------------------------------
extern "C" void kernel_launch(void* const* d_in, const int* in_sizes, int n_in,
                              void* d_out, int out_size) {
    const float* x       = (const float*)d_in[0];
    const float* plastic = (const float*)d_in[1];
    const float* prate   = (const float*)d_in[2];
    const float* fixed_w = (const float*)d_in[3];
    const float* fixed_b = (const float*)d_in[4];
    const float* hstr    = (const float*)d_in[5];

    float* combined = (float*)d_out;
    float* new_w    = (float*)d_out + COMBINED_ELEMS;

    static bool attr_done = false;
    if (!attr_done) {
        cudaFuncSetAttribute(gemm1_mma,
            cudaFuncAttributeMaxDynamicSharedMemorySize, G_SMEM_BYTES);
        cudaFuncSetAttribute(gemm2_mma,
            cudaFuncAttributeMaxDynamicSharedMemorySize, G_SMEM_BYTES);
        attr_done = true;
    }

    zero_acc_kernel<<<1, 1>>>();
    wsumtf_kernel<<<W_ELEMS / 4 / 256, 256>>>(fixed_w, plastic);
    xcvt_kernel<<<dim3(HDIM / 32, MTOT / 32), dim3(32, 8)>>>(x);

    gemm1_mma<<<dim3(HDIM / 128, MTOT / 128), 256, G_SMEM_BYTES>>>(
        fixed_b, combined);

    gemm2_mma<<<dim3(HDIM / 128, HDIM / 128), 256, G_SMEM_BYTES>>>(
        plastic, prate, hstr, new_w);

    scale_w_kernel<<<W_ELEMS / 4 / 256, 256>>>(new_w);
}